// round 3
// baseline (speedup 1.0000x reference)
#include <cuda_runtime.h>
#include <cstdint>

#define D      128
#define MAXN   100000
#define MAXE   1700000
#define SCAN_T 1024

// Scratch (allocation-free contract: __device__ globals)
__device__ float g_deg [MAXN];
__device__ float g_dinv[MAXN];
__device__ int   g_cnt [MAXN];
__device__ int   g_off [MAXN + 1];
__device__ int   g_cur [MAXN];
__device__ float g_h   [(size_t)MAXN * D];
__device__ int   g_ecol[MAXE];
__device__ float g_wn  [MAXE];
__device__ int   g_is64;

// ---------------------------------------------------------------------------
// Kernel 0: detect edge_index storage dtype (int32 vs int64).
// ---------------------------------------------------------------------------
__global__ void detect_dtype_kernel(const int* __restrict__ ei32, int n_i32) {
    __shared__ int any_nonzero;
    if (threadIdx.x == 0) any_nonzero = 0;
    __syncthreads();
    int n = min(1024, n_i32 / 2);
    for (int i = threadIdx.x; i < n; i += blockDim.x)
        if (ei32[2 * i + 1] != 0) any_nonzero = 1;
    __syncthreads();
    if (threadIdx.x == 0) g_is64 = (any_nonzero == 0) ? 1 : 0;
}

__device__ __forceinline__ int load_idx(const void* ei, int is64, size_t pos) {
    if (is64) return (int)((const long long*)ei)[pos];
    return ((const int*)ei)[pos];
}

// ---------------------------------------------------------------------------
// Kernel 1: deg[i]=1 (self loop), cnt[i]=0
// ---------------------------------------------------------------------------
__global__ void init_kernel(int N) {
    int i = blockIdx.x * blockDim.x + threadIdx.x;
    if (i < N) { g_deg[i] = 1.0f; g_cnt[i] = 0; }
}

// ---------------------------------------------------------------------------
// Kernel 2: deg[row] += w ; cnt[row]++
// ---------------------------------------------------------------------------
__global__ void accum_deg_kernel(const void* __restrict__ ei,
                                 const float* __restrict__ ew, int E) {
    int i = blockIdx.x * blockDim.x + threadIdx.x;
    if (i < E) {
        int r = load_idx(ei, g_is64, i);
        atomicAdd(&g_deg[r], ew[i]);
        atomicAdd(&g_cnt[r], 1);
    }
}

// ---------------------------------------------------------------------------
// Kernel 3: single-block exclusive scan of cnt -> off/cur ; dinv = rsqrt(deg)
// ---------------------------------------------------------------------------
__global__ void __launch_bounds__(SCAN_T)
scan_kernel(int N) {
    __shared__ int ws[32];
    const int t = threadIdx.x;
    const int chunk = (N + SCAN_T - 1) / SCAN_T;
    const int lo = t * chunk;
    const int hi = min(lo + chunk, N);

    int sum = 0;
    for (int i = lo; i < hi; i++) sum += g_cnt[i];

    // inclusive scan over 1024 partials
    int lane = t & 31, wid = t >> 5;
    int v = sum;
    #pragma unroll
    for (int d = 1; d < 32; d <<= 1) {
        int u = __shfl_up_sync(0xffffffff, v, d);
        if (lane >= d) v += u;
    }
    if (lane == 31) ws[wid] = v;
    __syncthreads();
    if (wid == 0) {
        int u = ws[lane];
        #pragma unroll
        for (int d = 1; d < 32; d <<= 1) {
            int p = __shfl_up_sync(0xffffffff, u, d);
            if (lane >= d) u += p;
        }
        ws[lane] = u;
    }
    __syncthreads();

    int base = (wid > 0 ? ws[wid - 1] : 0) + v - sum;  // exclusive prefix
    int off = base;
    for (int i = lo; i < hi; i++) {
        g_off[i] = off;
        g_cur[i] = off;
        off += g_cnt[i];
        float dg = g_deg[i];
        g_dinv[i] = (dg > 0.0f) ? rsqrtf(dg) : 0.0f;
    }
    if (t == SCAN_T - 1) g_off[N] = off;
}

// ---------------------------------------------------------------------------
// Kernel 4: bucket edges by row (CSR), pre-normalizing the weight.
// ---------------------------------------------------------------------------
__global__ void bucket_kernel(const void* __restrict__ ei,
                              const float* __restrict__ ew, int E) {
    int i = blockIdx.x * blockDim.x + threadIdx.x;
    if (i < E) {
        const int is64 = g_is64;
        int r = load_idx(ei, is64, i);
        int c = load_idx(ei, is64, (size_t)E + i);
        int pos = atomicAdd(&g_cur[r], 1);
        g_ecol[pos] = c;
        g_wn[pos]   = ew[i] * g_dinv[r] * g_dinv[c];
    }
}

// ---------------------------------------------------------------------------
// Kernel 5: h = x @ W via packed fma.rn.f32x2 (two rows per accumulator).
// Block = 128 threads (one per output column), 32 rows per block.
// smem: xs[t-feature][row] row-pairs contiguous => ulonglong2 loads give
// ready-packed f32x2 operands, broadcast across the warp.
// ---------------------------------------------------------------------------
#define GR 32          // rows per block
#define XSTRIDE 36     // floats per feature row (32 data + 4 pad, 16B aligned)

__global__ void __launch_bounds__(D)
gemm_kernel(const float* __restrict__ x,
            const float* __restrict__ W, int N) {
    __shared__ __align__(16) float xs[D * XSTRIDE];
    const int t  = threadIdx.x;           // output column / feature index
    const int r0 = blockIdx.x * GR;

    // preload: xs[t*XSTRIDE + j] = x[r0+j][t]
    #pragma unroll
    for (int j = 0; j < GR; j++) {
        int r = r0 + j;
        xs[t * XSTRIDE + j] = (r < N) ? x[(size_t)r * D + t] : 0.0f;
    }
    __syncthreads();

    unsigned long long acc[GR / 2];
    #pragma unroll
    for (int j = 0; j < GR / 2; j++) acc[j] = 0ull;

    #pragma unroll 2
    for (int k = 0; k < D; k++) {
        float w = __ldg(&W[k * D + t]);
        unsigned long long w2;
        asm("mov.b64 %0, {%1, %1};" : "=l"(w2) : "f"(w));
        const ulonglong2* row = (const ulonglong2*)(xs + k * XSTRIDE);
        #pragma unroll
        for (int p = 0; p < GR / 4; p++) {       // 8 LDS.128, each = 2 packed pairs
            ulonglong2 q = row[p];
            asm("fma.rn.f32x2 %0, %1, %2, %0;" : "+l"(acc[2*p    ]) : "l"(q.x), "l"(w2));
            asm("fma.rn.f32x2 %0, %1, %2, %0;" : "+l"(acc[2*p + 1]) : "l"(q.y), "l"(w2));
        }
    }

    #pragma unroll
    for (int j = 0; j < GR / 2; j++) {
        float lo, hi;
        asm("mov.b64 {%0, %1}, %2;" : "=f"(lo), "=f"(hi) : "l"(acc[j]));
        int r = r0 + 2 * j;
        if (r < N)     g_h[(size_t)r * D + t]       = lo;
        if (r + 1 < N) g_h[(size_t)(r + 1) * D + t] = hi;
    }
}

// ---------------------------------------------------------------------------
// Kernel 6: per-row gather. One warp per row; lane owns 4 columns (float4).
// acc = dinv[r]^2 * h[r]  +  sum_edges w_n * h[col]  + bias.  Single write.
// ---------------------------------------------------------------------------
__global__ void __launch_bounds__(128)
gather_kernel(const float* __restrict__ bias,
              float* __restrict__ out, int N) {
    const int warp = (blockIdx.x * blockDim.x + threadIdx.x) >> 5;
    const int lane = threadIdx.x & 31;
    if (warp >= N) return;
    const int row = warp;

    const int s = g_off[row];
    const int e = g_off[row + 1];

    // self-loop term
    float dv = g_dinv[row];
    float ws = dv * dv;
    float4 hv = ((const float4*)(g_h + (size_t)row * D))[lane];
    float4 acc = make_float4(ws * hv.x, ws * hv.y, ws * hv.z, ws * hv.w);

    // software-pipelined edge loop (index prefetch hides gather latency)
    int j = s;
    int   c0 = 0; float w0 = 0.0f;
    if (j < e) { c0 = g_ecol[j]; w0 = g_wn[j]; }
    while (j < e) {
        int jn = j + 1;
        int c1 = 0; float w1 = 0.0f;
        if (jn < e) { c1 = g_ecol[jn]; w1 = g_wn[jn]; }
        float4 v = ((const float4*)(g_h + (size_t)c0 * D))[lane];
        acc.x += w0 * v.x; acc.y += w0 * v.y;
        acc.z += w0 * v.z; acc.w += w0 * v.w;
        c0 = c1; w0 = w1; j = jn;
    }

    float4 b = ((const float4*)bias)[lane];
    acc.x += b.x; acc.y += b.y; acc.z += b.z; acc.w += b.w;
    ((float4*)(out + (size_t)row * D))[lane] = acc;
}

// ---------------------------------------------------------------------------
extern "C" void kernel_launch(void* const* d_in, const int* in_sizes, int n_in,
                              void* d_out, int out_size) {
    const float* x    = (const float*)d_in[0];    // [N, 128]
    const void*  ei   = d_in[1];                  // [2, E] int64-or-int32
    const float* ew   = (const float*)d_in[2];    // [E]
    const float* W    = (const float*)d_in[3];    // [128, 128]
    const float* bias = (const float*)d_in[4];    // [128]
    float*       out  = (float*)d_out;            // [N, 128]

    const int N = in_sizes[0] / D;
    const int E = in_sizes[2];

    detect_dtype_kernel<<<1, 256>>>((const int*)ei, 2 * E);
    init_kernel<<<(N + 255) / 256, 256>>>(N);
    accum_deg_kernel<<<(E + 255) / 256, 256>>>(ei, ew, E);
    scan_kernel<<<1, SCAN_T>>>(N);
    bucket_kernel<<<(E + 255) / 256, 256>>>(ei, ew, E);
    gemm_kernel<<<(N + GR - 1) / GR, D>>>(x, W, N);

    int warps_needed = N;                      // one warp per row
    int blocks = (warps_needed * 32 + 127) / 128;
    gather_kernel<<<blocks, 128>>>(bias, out, N);
}

// round 4
// speedup vs baseline: 2.0499x; 2.0499x over previous
#include <cuda_runtime.h>
#include <cstdint>

#define D       128
#define MAXN    100000
#define MAXE    1700000
#define TILE    1024
#define MAXB    ((MAXN + TILE - 1) / TILE)   // 98

// Scratch (allocation-free contract: __device__ globals)
__device__ float g_deg [MAXN];
__device__ float g_dinv[MAXN];
__device__ int   g_cnt [MAXN];
__device__ int   g_off [MAXN + 1];
__device__ int   g_cur [MAXN];
__device__ int   g_bsum[MAXB];
__device__ int   g_bpre[MAXB];
__device__ float g_h   [(size_t)MAXN * D];
__device__ int   g_ecol[MAXE];
__device__ float g_wn  [MAXE];
__device__ int   g_is64;

// ---------------------------------------------------------------------------
// Kernel 0: detect edge_index storage dtype (int32 vs int64).
// ---------------------------------------------------------------------------
__global__ void detect_dtype_kernel(const int* __restrict__ ei32, int n_i32) {
    __shared__ int any_nonzero;
    if (threadIdx.x == 0) any_nonzero = 0;
    __syncthreads();
    int n = min(1024, n_i32 / 2);
    for (int i = threadIdx.x; i < n; i += blockDim.x)
        if (ei32[2 * i + 1] != 0) any_nonzero = 1;
    __syncthreads();
    if (threadIdx.x == 0) g_is64 = (any_nonzero == 0) ? 1 : 0;
}

__device__ __forceinline__ int load_idx(const void* ei, int is64, size_t pos) {
    if (is64) return (int)((const long long*)ei)[pos];
    return ((const int*)ei)[pos];
}

// ---------------------------------------------------------------------------
// Kernel 1: deg[i]=1 (self loop), cnt[i]=0
// ---------------------------------------------------------------------------
__global__ void init_kernel(int N) {
    int i = blockIdx.x * blockDim.x + threadIdx.x;
    if (i < N) { g_deg[i] = 1.0f; g_cnt[i] = 0; }
}

// ---------------------------------------------------------------------------
// Kernel 2: deg[row] += w ; cnt[row]++
// ---------------------------------------------------------------------------
__global__ void accum_deg_kernel(const void* __restrict__ ei,
                                 const float* __restrict__ ew, int E) {
    int i = blockIdx.x * blockDim.x + threadIdx.x;
    if (i < E) {
        int r = load_idx(ei, g_is64, i);
        atomicAdd(&g_deg[r], ew[i]);
        atomicAdd(&g_cnt[r], 1);
    }
}

// ---------------------------------------------------------------------------
// Hierarchical exclusive scan of g_cnt (3 phases, fully parallel)
// ---------------------------------------------------------------------------
__device__ __forceinline__ int warp_incl_scan(int v) {
    #pragma unroll
    for (int d = 1; d < 32; d <<= 1) {
        int u = __shfl_up_sync(0xffffffff, v, d);
        if ((threadIdx.x & 31) >= d) v += u;
    }
    return v;
}

// Phase 1: per-block sums
__global__ void __launch_bounds__(TILE)
scan_pass1(int N) {
    __shared__ int ws[32];
    int i = blockIdx.x * TILE + threadIdx.x;
    int v = (i < N) ? g_cnt[i] : 0;
    int lane = threadIdx.x & 31, wid = threadIdx.x >> 5;
    int s = warp_incl_scan(v);
    if (lane == 31) ws[wid] = s;
    __syncthreads();
    if (wid == 0) {
        int u = ws[lane];
        u = warp_incl_scan(u);
        if (lane == 31) g_bsum[blockIdx.x] = u;
    }
}

// Phase 2: scan block sums (nb <= 1024), write total to g_off[N]
__global__ void __launch_bounds__(TILE)
scan_pass2(int nb, int N) {
    __shared__ int ws[32];
    int t = threadIdx.x;
    int v = (t < nb) ? g_bsum[t] : 0;
    int lane = t & 31, wid = t >> 5;
    int s = warp_incl_scan(v);
    if (lane == 31) ws[wid] = s;
    __syncthreads();
    if (wid == 0) ws[lane] = warp_incl_scan(ws[lane]);
    __syncthreads();
    int incl = s + (wid > 0 ? ws[wid - 1] : 0);
    if (t < nb) g_bpre[t] = incl - v;          // exclusive block prefix
    if (t == nb - 1) g_off[N] = incl;          // grand total
}

// Phase 3: intra-block exclusive scan + block prefix; also dinv = rsqrt(deg)
__global__ void __launch_bounds__(TILE)
scan_pass3(int N) {
    __shared__ int ws[32];
    int i = blockIdx.x * TILE + threadIdx.x;
    int v = (i < N) ? g_cnt[i] : 0;
    int lane = threadIdx.x & 31, wid = threadIdx.x >> 5;
    int s = warp_incl_scan(v);
    if (lane == 31) ws[wid] = s;
    __syncthreads();
    if (wid == 0) ws[lane] = warp_incl_scan(ws[lane]);
    __syncthreads();
    int excl = s - v + (wid > 0 ? ws[wid - 1] : 0) + g_bpre[blockIdx.x];
    if (i < N) {
        g_off[i] = excl;
        g_cur[i] = excl;
        float dg = g_deg[i];
        g_dinv[i] = (dg > 0.0f) ? rsqrtf(dg) : 0.0f;
    }
}

// ---------------------------------------------------------------------------
// Kernel 4: bucket edges by row (CSR), pre-normalizing the weight.
// ---------------------------------------------------------------------------
__global__ void bucket_kernel(const void* __restrict__ ei,
                              const float* __restrict__ ew, int E) {
    int i = blockIdx.x * blockDim.x + threadIdx.x;
    if (i < E) {
        const int is64 = g_is64;
        int r = load_idx(ei, is64, i);
        int c = load_idx(ei, is64, (size_t)E + i);
        int pos = atomicAdd(&g_cur[r], 1);
        g_ecol[pos] = c;
        g_wn[pos]   = ew[i] * g_dinv[r] * g_dinv[c];
    }
}

// ---------------------------------------------------------------------------
// Kernel 5: h = x @ W via packed fma.rn.f32x2 (two rows per accumulator).
// ---------------------------------------------------------------------------
#define GR 32          // rows per block
#define XSTRIDE 36     // floats per feature row (32 data + 4 pad, 16B aligned)

__global__ void __launch_bounds__(D)
gemm_kernel(const float* __restrict__ x,
            const float* __restrict__ W, int N) {
    __shared__ __align__(16) float xs[D * XSTRIDE];
    const int t  = threadIdx.x;           // output column / feature index
    const int r0 = blockIdx.x * GR;

    #pragma unroll
    for (int j = 0; j < GR; j++) {
        int r = r0 + j;
        xs[t * XSTRIDE + j] = (r < N) ? x[(size_t)r * D + t] : 0.0f;
    }
    __syncthreads();

    unsigned long long acc[GR / 2];
    #pragma unroll
    for (int j = 0; j < GR / 2; j++) acc[j] = 0ull;

    #pragma unroll 2
    for (int k = 0; k < D; k++) {
        float w = __ldg(&W[k * D + t]);
        unsigned long long w2;
        asm("mov.b64 %0, {%1, %1};" : "=l"(w2) : "f"(w));
        const ulonglong2* row = (const ulonglong2*)(xs + k * XSTRIDE);
        #pragma unroll
        for (int p = 0; p < GR / 4; p++) {
            ulonglong2 q = row[p];
            asm("fma.rn.f32x2 %0, %1, %2, %0;" : "+l"(acc[2*p    ]) : "l"(q.x), "l"(w2));
            asm("fma.rn.f32x2 %0, %1, %2, %0;" : "+l"(acc[2*p + 1]) : "l"(q.y), "l"(w2));
        }
    }

    #pragma unroll
    for (int j = 0; j < GR / 2; j++) {
        float lo, hi;
        asm("mov.b64 {%0, %1}, %2;" : "=f"(lo), "=f"(hi) : "l"(acc[j]));
        int r = r0 + 2 * j;
        if (r < N)     g_h[(size_t)r * D + t]       = lo;
        if (r + 1 < N) g_h[(size_t)(r + 1) * D + t] = hi;
    }
}

// ---------------------------------------------------------------------------
// Kernel 6: per-row gather. One warp per row; lane owns 4 columns (float4).
// ---------------------------------------------------------------------------
__global__ void __launch_bounds__(128)
gather_kernel(const float* __restrict__ bias,
              float* __restrict__ out, int N) {
    const int warp = (blockIdx.x * blockDim.x + threadIdx.x) >> 5;
    const int lane = threadIdx.x & 31;
    if (warp >= N) return;
    const int row = warp;

    const int s = g_off[row];
    const int e = g_off[row + 1];

    float dv = g_dinv[row];
    float ws = dv * dv;
    float4 hv = ((const float4*)(g_h + (size_t)row * D))[lane];
    float4 acc = make_float4(ws * hv.x, ws * hv.y, ws * hv.z, ws * hv.w);

    int j = s;
    int   c0 = 0; float w0 = 0.0f;
    if (j < e) { c0 = g_ecol[j]; w0 = g_wn[j]; }
    while (j < e) {
        int jn = j + 1;
        int c1 = 0; float w1 = 0.0f;
        if (jn < e) { c1 = g_ecol[jn]; w1 = g_wn[jn]; }
        float4 v = ((const float4*)(g_h + (size_t)c0 * D))[lane];
        acc.x += w0 * v.x; acc.y += w0 * v.y;
        acc.z += w0 * v.z; acc.w += w0 * v.w;
        c0 = c1; w0 = w1; j = jn;
    }

    float4 b = ((const float4*)bias)[lane];
    acc.x += b.x; acc.y += b.y; acc.z += b.z; acc.w += b.w;
    ((float4*)(out + (size_t)row * D))[lane] = acc;
}

// ---------------------------------------------------------------------------
extern "C" void kernel_launch(void* const* d_in, const int* in_sizes, int n_in,
                              void* d_out, int out_size) {
    const float* x    = (const float*)d_in[0];    // [N, 128]
    const void*  ei   = d_in[1];                  // [2, E] int64-or-int32
    const float* ew   = (const float*)d_in[2];    // [E]
    const float* W    = (const float*)d_in[3];    // [128, 128]
    const float* bias = (const float*)d_in[4];    // [128]
    float*       out  = (float*)d_out;            // [N, 128]

    const int N = in_sizes[0] / D;
    const int E = in_sizes[2];
    const int nb = (N + TILE - 1) / TILE;

    detect_dtype_kernel<<<1, 256>>>((const int*)ei, 2 * E);
    init_kernel<<<(N + 255) / 256, 256>>>(N);
    accum_deg_kernel<<<(E + 255) / 256, 256>>>(ei, ew, E);
    scan_pass1<<<nb, TILE>>>(N);
    scan_pass2<<<1, TILE>>>(nb, N);
    scan_pass3<<<nb, TILE>>>(N);
    bucket_kernel<<<(E + 255) / 256, 256>>>(ei, ew, E);
    gemm_kernel<<<(N + GR - 1) / GR, D>>>(x, W, N);

    int blocks = (N * 32 + 127) / 128;            // one warp per row
    gather_kernel<<<blocks, 128>>>(bias, out, N);
}

// round 5
// speedup vs baseline: 2.2378x; 1.0916x over previous
#include <cuda_runtime.h>
#include <cuda_fp16.h>
#include <cstdint>

#define D       128
#define MAXN    100000
#define MAXE    1700000
#define TILE    1024
#define MAXB    ((MAXN + TILE - 1) / TILE)   // 98

// Scratch (allocation-free contract: __device__ globals)
__device__ float g_deg [MAXN];
__device__ float g_dinv[MAXN];
__device__ int   g_cnt [MAXN];
__device__ int   g_off [MAXN + 1];
__device__ int   g_cur [MAXN];
__device__ int   g_bsum[MAXB];
__device__ int   g_bpre[MAXB];
__device__ __half g_h16[(size_t)MAXN * D];
__device__ int2  g_edge[MAXE];               // packed {col, w_bits}
__device__ int   g_is64;

// ---------------------------------------------------------------------------
// Kernel 0: detect edge_index storage dtype (int32 vs int64).
// ---------------------------------------------------------------------------
__global__ void detect_dtype_kernel(const int* __restrict__ ei32, int n_i32) {
    __shared__ int any_nonzero;
    if (threadIdx.x == 0) any_nonzero = 0;
    __syncthreads();
    int n = min(1024, n_i32 / 2);
    for (int i = threadIdx.x; i < n; i += blockDim.x)
        if (ei32[2 * i + 1] != 0) any_nonzero = 1;
    __syncthreads();
    if (threadIdx.x == 0) g_is64 = (any_nonzero == 0) ? 1 : 0;
}

__device__ __forceinline__ int load_idx(const void* ei, int is64, size_t pos) {
    if (is64) return (int)((const long long*)ei)[pos];
    return ((const int*)ei)[pos];
}

// ---------------------------------------------------------------------------
// Kernel 1: deg[i]=1 (self loop), cnt[i]=0
// ---------------------------------------------------------------------------
__global__ void init_kernel(int N) {
    int i = blockIdx.x * blockDim.x + threadIdx.x;
    if (i < N) { g_deg[i] = 1.0f; g_cnt[i] = 0; }
}

// ---------------------------------------------------------------------------
// Kernel 2: deg[row] += w ; cnt[row]++
// ---------------------------------------------------------------------------
__global__ void accum_deg_kernel(const void* __restrict__ ei,
                                 const float* __restrict__ ew, int E) {
    int i = blockIdx.x * blockDim.x + threadIdx.x;
    if (i < E) {
        int r = load_idx(ei, g_is64, i);
        atomicAdd(&g_deg[r], ew[i]);
        atomicAdd(&g_cnt[r], 1);
    }
}

// ---------------------------------------------------------------------------
// Hierarchical exclusive scan of g_cnt (3 phases)
// ---------------------------------------------------------------------------
__device__ __forceinline__ int warp_incl_scan(int v) {
    #pragma unroll
    for (int d = 1; d < 32; d <<= 1) {
        int u = __shfl_up_sync(0xffffffff, v, d);
        if ((threadIdx.x & 31) >= d) v += u;
    }
    return v;
}

__global__ void __launch_bounds__(TILE)
scan_pass1(int N) {
    __shared__ int ws[32];
    int i = blockIdx.x * TILE + threadIdx.x;
    int v = (i < N) ? g_cnt[i] : 0;
    int lane = threadIdx.x & 31, wid = threadIdx.x >> 5;
    int s = warp_incl_scan(v);
    if (lane == 31) ws[wid] = s;
    __syncthreads();
    if (wid == 0) {
        int u = ws[lane];
        u = warp_incl_scan(u);
        if (lane == 31) g_bsum[blockIdx.x] = u;
    }
}

__global__ void __launch_bounds__(TILE)
scan_pass2(int nb, int N) {
    __shared__ int ws[32];
    int t = threadIdx.x;
    int v = (t < nb) ? g_bsum[t] : 0;
    int lane = t & 31, wid = t >> 5;
    int s = warp_incl_scan(v);
    if (lane == 31) ws[wid] = s;
    __syncthreads();
    if (wid == 0) ws[lane] = warp_incl_scan(ws[lane]);
    __syncthreads();
    int incl = s + (wid > 0 ? ws[wid - 1] : 0);
    if (t < nb) g_bpre[t] = incl - v;
    if (t == nb - 1) g_off[N] = incl;
}

__global__ void __launch_bounds__(TILE)
scan_pass3(int N) {
    __shared__ int ws[32];
    int i = blockIdx.x * TILE + threadIdx.x;
    int v = (i < N) ? g_cnt[i] : 0;
    int lane = threadIdx.x & 31, wid = threadIdx.x >> 5;
    int s = warp_incl_scan(v);
    if (lane == 31) ws[wid] = s;
    __syncthreads();
    if (wid == 0) ws[lane] = warp_incl_scan(ws[lane]);
    __syncthreads();
    int excl = s - v + (wid > 0 ? ws[wid - 1] : 0) + g_bpre[blockIdx.x];
    if (i < N) {
        g_off[i] = excl;
        g_cur[i] = excl;
        float dg = g_deg[i];
        g_dinv[i] = (dg > 0.0f) ? rsqrtf(dg) : 0.0f;
    }
}

// ---------------------------------------------------------------------------
// Kernel 4: bucket edges by row (CSR), pre-normalizing the weight.
// Packed 8-byte record per edge: {col, weight-bits}.
// ---------------------------------------------------------------------------
__global__ void bucket_kernel(const void* __restrict__ ei,
                              const float* __restrict__ ew, int E) {
    int i = blockIdx.x * blockDim.x + threadIdx.x;
    if (i < E) {
        const int is64 = g_is64;
        int r = load_idx(ei, is64, i);
        int c = load_idx(ei, is64, (size_t)E + i);
        int pos = atomicAdd(&g_cur[r], 1);
        float wn = ew[i] * g_dinv[r] * g_dinv[c];
        g_edge[pos] = make_int2(c, __float_as_int(wn));
    }
}

// ---------------------------------------------------------------------------
// Kernel 5: h = x @ W via packed fma.rn.f32x2; store h as fp16.
// ---------------------------------------------------------------------------
#define GR 32          // rows per block
#define XSTRIDE 36     // floats per feature row (32 data + 4 pad, 16B aligned)

__global__ void __launch_bounds__(D)
gemm_kernel(const float* __restrict__ x,
            const float* __restrict__ W, int N) {
    __shared__ __align__(16) float xs[D * XSTRIDE];
    const int t  = threadIdx.x;           // output column / feature index
    const int r0 = blockIdx.x * GR;

    #pragma unroll
    for (int j = 0; j < GR; j++) {
        int r = r0 + j;
        xs[t * XSTRIDE + j] = (r < N) ? x[(size_t)r * D + t] : 0.0f;
    }
    __syncthreads();

    unsigned long long acc[GR / 2];
    #pragma unroll
    for (int j = 0; j < GR / 2; j++) acc[j] = 0ull;

    #pragma unroll 2
    for (int k = 0; k < D; k++) {
        float w = __ldg(&W[k * D + t]);
        unsigned long long w2;
        asm("mov.b64 %0, {%1, %1};" : "=l"(w2) : "f"(w));
        const ulonglong2* row = (const ulonglong2*)(xs + k * XSTRIDE);
        #pragma unroll
        for (int p = 0; p < GR / 4; p++) {
            ulonglong2 q = row[p];
            asm("fma.rn.f32x2 %0, %1, %2, %0;" : "+l"(acc[2*p    ]) : "l"(q.x), "l"(w2));
            asm("fma.rn.f32x2 %0, %1, %2, %0;" : "+l"(acc[2*p + 1]) : "l"(q.y), "l"(w2));
        }
    }

    #pragma unroll
    for (int j = 0; j < GR / 2; j++) {
        float lo, hi;
        asm("mov.b64 {%0, %1}, %2;" : "=f"(lo), "=f"(hi) : "l"(acc[j]));
        int r = r0 + 2 * j;
        if (r < N)     g_h16[(size_t)r * D + t]       = __float2half_rn(lo);
        if (r + 1 < N) g_h16[(size_t)(r + 1) * D + t] = __float2half_rn(hi);
    }
}

// ---------------------------------------------------------------------------
// Kernel 6: per-row gather (fp16 h). One warp per row; lane owns 4 columns.
// acc = dinv[r]^2*h[r] + sum w_n*h[col] + bias; fp32 accumulation.
// ---------------------------------------------------------------------------
__device__ __forceinline__ float4 load_h4(int row, int lane) {
    // 4 halves = 8 bytes per lane
    uint2 raw = ((const uint2*)(g_h16 + (size_t)row * D))[lane];
    __half2 a = *(__half2*)&raw.x;
    __half2 b = *(__half2*)&raw.y;
    float2 fa = __half22float2(a);
    float2 fb = __half22float2(b);
    return make_float4(fa.x, fa.y, fb.x, fb.y);
}

__global__ void __launch_bounds__(128)
gather_kernel(const float* __restrict__ bias,
              float* __restrict__ out, int N) {
    const int warp = (blockIdx.x * blockDim.x + threadIdx.x) >> 5;
    const int lane = threadIdx.x & 31;
    if (warp >= N) return;
    const int row = warp;

    const int s = g_off[row];
    const int e = g_off[row + 1];

    float dv = g_dinv[row];
    float ws = dv * dv;
    float4 hv = load_h4(row, lane);
    float4 acc = make_float4(ws * hv.x, ws * hv.y, ws * hv.z, ws * hv.w);

    // software-pipelined edge loop (record prefetch hides gather latency)
    int j = s;
    int2 e0 = make_int2(0, 0);
    if (j < e) e0 = g_edge[j];
    while (j < e) {
        int jn = j + 1;
        int2 e1 = make_int2(0, 0);
        if (jn < e) e1 = g_edge[jn];
        float w0 = __int_as_float(e0.y);
        float4 v = load_h4(e0.x, lane);
        acc.x += w0 * v.x; acc.y += w0 * v.y;
        acc.z += w0 * v.z; acc.w += w0 * v.w;
        e0 = e1; j = jn;
    }

    float4 b = ((const float4*)bias)[lane];
    acc.x += b.x; acc.y += b.y; acc.z += b.z; acc.w += b.w;
    ((float4*)(out + (size_t)row * D))[lane] = acc;
}

// ---------------------------------------------------------------------------
extern "C" void kernel_launch(void* const* d_in, const int* in_sizes, int n_in,
                              void* d_out, int out_size) {
    const float* x    = (const float*)d_in[0];    // [N, 128]
    const void*  ei   = d_in[1];                  // [2, E] int64-or-int32
    const float* ew   = (const float*)d_in[2];    // [E]
    const float* W    = (const float*)d_in[3];    // [128, 128]
    const float* bias = (const float*)d_in[4];    // [128]
    float*       out  = (float*)d_out;            // [N, 128]

    const int N = in_sizes[0] / D;
    const int E = in_sizes[2];
    const int nb = (N + TILE - 1) / TILE;

    detect_dtype_kernel<<<1, 256>>>((const int*)ei, 2 * E);
    init_kernel<<<(N + 255) / 256, 256>>>(N);
    accum_deg_kernel<<<(E + 255) / 256, 256>>>(ei, ew, E);
    scan_pass1<<<nb, TILE>>>(N);
    scan_pass2<<<1, TILE>>>(nb, N);
    scan_pass3<<<nb, TILE>>>(N);
    bucket_kernel<<<(E + 255) / 256, 256>>>(ei, ew, E);
    gemm_kernel<<<(N + GR - 1) / GR, D>>>(x, W, N);

    int blocks = (N * 32 + 127) / 128;            // one warp per row
    gather_kernel<<<blocks, 128>>>(bias, out, N);
}